// round 4
// baseline (speedup 1.0000x reference)
#include <cuda_runtime.h>
#include <cstdint>
#include <cstddef>

#define N_NODES 100000
#define N_GRAPHS 64
#define HIDC 64

// ---------------------------------------------------------------------------
// Scratch (static device globals — no allocation anywhere)
// ---------------------------------------------------------------------------
__device__ float g_Y[(size_t)N_NODES * HIDC];      // x @ w_rel   (25.6 MB)
__device__ float g_AGG_A[(size_t)N_NODES * HIDC];  // aggregation ping (25.6 MB)
__device__ float g_AGG_B[(size_t)N_NODES * HIDC];  // aggregation pong (25.6 MB)
__device__ float g_sums[N_GRAPHS * HIDC];
__device__ float g_counts[N_GRAPHS];
__device__ int   g_idx64;                          // 1 if indices are int64

// ---------------------------------------------------------------------------
// Vector RED (16B atomic add, sm_90+)
// ---------------------------------------------------------------------------
__device__ __forceinline__ void red_add_f4(float* addr, float4 v) {
    asm volatile("red.global.add.v4.f32 [%0], {%1, %2, %3, %4};"
                 :: "l"(addr), "f"(v.x), "f"(v.y), "f"(v.z), "f"(v.w)
                 : "memory");
}

// ---------------------------------------------------------------------------
// Detect index dtype: int64 (little-endian, nonneg, < 2^31) has zero odd words.
// For int32 data these words are random node ids (P(all zero) ~ 0).
// ---------------------------------------------------------------------------
__global__ void detect_kernel(const int* __restrict__ ei) {
    int z = ei[1] | ei[3] | ei[5] | ei[7] | ei[9] | ei[11] | ei[13] | ei[15];
    g_idx64 = (z == 0) ? 1 : 0;
}

// ---------------------------------------------------------------------------
// Fused projection:
//   Y[n]   = act(X[n]) @ Wrel
//   AGG[n] = act(X[n]) @ Wroot + b_rel      (act = ReLU for layers 1,2)
// Register-tiled: block = 256 threads, tile = 64 nodes x 64 out-ch.
// Thread owns 4 nodes x 4 channels x 2 matrices (32 accumulators).
// Weights + transposed x-tile live in smem; all inner loads are float4.
// ---------------------------------------------------------------------------
template<int IN, bool RELU_IN>
__global__ __launch_bounds__(256)
void proj_kernel(const float* __restrict__ X,
                 const float* __restrict__ Wrel,
                 const float* __restrict__ Wroot,
                 const float* __restrict__ Brel,
                 float* __restrict__ Y,
                 float* __restrict__ AGG)
{
    extern __shared__ float smem[];
    float* wr = smem;                 // IN*64
    float* wo = wr + IN * 64;         // IN*64
    float* xs = wo + IN * 64;         // IN*68 (padded, transposed: xs[i][node])
    const int XS_STRIDE = 68;

    for (int i = threadIdx.x; i < IN * 64; i += 256) {
        wr[i] = Wrel[i];
        wo[i] = Wroot[i];
    }

    const int tid = threadIdx.x;
    const int chg = tid & 15;   // 4-channel group: channels chg*4 .. chg*4+3
    const int ng  = tid >> 4;   // 4-node group within 64-node tile

    const float b0 = Brel[chg * 4 + 0];
    const float b1 = Brel[chg * 4 + 1];
    const float b2 = Brel[chg * 4 + 2];
    const float b3 = Brel[chg * 4 + 3];

    const int n_tiles = (N_NODES + 63) / 64;
    for (int tile = blockIdx.x; tile < n_tiles; tile += gridDim.x) {
        const int base = tile * 64;
        __syncthreads();  // weights visible (first iter) / previous xs done

        // Load 64 rows of X, transposed into xs. 4 threads per node, each
        // streams a contiguous IN/4 chunk (one 128B line per lane for IN=128).
        {
            const int node_l = tid >> 2;   // 0..63
            const int part   = tid & 3;    // 0..3
            const int node   = base + node_l;
            const bool valid = node < N_NODES;
            const float* xrow = X + (size_t)node * IN + part * (IN / 4);
            for (int k = 0; k < IN / 4; k++) {
                float v = valid ? xrow[k] : 0.0f;
                if (RELU_IN) v = fmaxf(v, 0.0f);
                xs[(part * (IN / 4) + k) * XS_STRIDE + node_l] = v;
            }
        }
        __syncthreads();

        float acc_r[4][4], acc_o[4][4];
        #pragma unroll
        for (int a = 0; a < 4; a++)
            #pragma unroll
            for (int c = 0; c < 4; c++) { acc_r[a][c] = 0.0f; acc_o[a][c] = 0.0f; }

        #pragma unroll 4
        for (int i = 0; i < IN; i++) {
            const float4 xv  = *(const float4*)(xs + i * XS_STRIDE + (ng << 2));
            const float4 wrv = *(const float4*)(wr + (i << 6) + (chg << 2));
            const float4 wov = *(const float4*)(wo + (i << 6) + (chg << 2));
            #define PROJ_STEP(a, XA)                                          \
                acc_r[a][0] = fmaf(XA, wrv.x, acc_r[a][0]);                   \
                acc_r[a][1] = fmaf(XA, wrv.y, acc_r[a][1]);                   \
                acc_r[a][2] = fmaf(XA, wrv.z, acc_r[a][2]);                   \
                acc_r[a][3] = fmaf(XA, wrv.w, acc_r[a][3]);                   \
                acc_o[a][0] = fmaf(XA, wov.x, acc_o[a][0]);                   \
                acc_o[a][1] = fmaf(XA, wov.y, acc_o[a][1]);                   \
                acc_o[a][2] = fmaf(XA, wov.z, acc_o[a][2]);                   \
                acc_o[a][3] = fmaf(XA, wov.w, acc_o[a][3]);
            PROJ_STEP(0, xv.x)
            PROJ_STEP(1, xv.y)
            PROJ_STEP(2, xv.z)
            PROJ_STEP(3, xv.w)
            #undef PROJ_STEP
        }

        const int node0 = base + ng * 4;
        #pragma unroll
        for (int a = 0; a < 4; a++) {
            const int node = node0 + a;
            if (node < N_NODES) {
                float* yp = Y   + (size_t)node * 64 + chg * 4;
                float* ap = AGG + (size_t)node * 64 + chg * 4;
                *(float4*)yp = make_float4(acc_r[a][0], acc_r[a][1],
                                           acc_r[a][2], acc_r[a][3]);
                *(float4*)ap = make_float4(acc_o[a][0] + b0, acc_o[a][1] + b1,
                                           acc_o[a][2] + b2, acc_o[a][3] + b3);
            }
        }
    }
}

// ---------------------------------------------------------------------------
// Edge scatter: AGG[dst] += Y[src]. 16 lanes/edge, one float4 RED each.
// Y and AGG (25.6 MB each) are L2-resident.
// ---------------------------------------------------------------------------
__global__ __launch_bounds__(256)
void scatter_kernel(const float4* __restrict__ Y,
                    const void* __restrict__ ei,
                    float* __restrict__ AGG,
                    int n_edges)
{
    const int t = blockIdx.x * 256 + threadIdx.x;
    const int e = t >> 4;
    if (e >= n_edges) return;
    const int q = t & 15;

    int s, d;
    if (g_idx64) {
        const long long* p = (const long long*)ei;
        s = (int)p[e];
        d = (int)p[e + n_edges];
    } else {
        const int* p = (const int*)ei;
        s = p[e];
        d = p[e + n_edges];
    }
    const float4 v = Y[(size_t)s * 16 + q];
    red_add_f4(AGG + (size_t)d * 64 + q * 4, v);
}

// ---------------------------------------------------------------------------
// Pool prep + pool + head
// ---------------------------------------------------------------------------
__global__ void zero_pool_kernel() {
    const int t = threadIdx.x;
    for (int i = t; i < N_GRAPHS * HIDC; i += 256) g_sums[i] = 0.0f;
    if (t < N_GRAPHS) g_counts[t] = 0.0f;
}

__global__ __launch_bounds__(256)
void pool_kernel(const float* __restrict__ H, const void* __restrict__ batch)
{
    const int t = blockIdx.x * 256 + threadIdx.x;
    const int node = t >> 4;
    if (node >= N_NODES) return;
    const int q = t & 15;

    int g;
    if (g_idx64) g = (int)((const long long*)batch)[node];
    else         g = ((const int*)batch)[node];

    float4 v = ((const float4*)H)[(size_t)node * 16 + q];
    v.x = fmaxf(v.x, 0.0f);  // final-layer ReLU fused here
    v.y = fmaxf(v.y, 0.0f);
    v.z = fmaxf(v.z, 0.0f);
    v.w = fmaxf(v.w, 0.0f);
    red_add_f4(g_sums + g * 64 + q * 4, v);
    if (q == 0) atomicAdd(&g_counts[g], 1.0f);
}

__global__ void head_kernel(const float* __restrict__ W1, const float* __restrict__ B1,
                            const float* __restrict__ W2, const float* __restrict__ B2,
                            float* __restrict__ out)
{
    const int g = threadIdx.x;
    if (g >= N_GRAPHS) return;
    const float inv = 1.0f / fmaxf(g_counts[g], 1.0f);
    float p[64];
    #pragma unroll
    for (int i = 0; i < 64; i++) p[i] = g_sums[g * 64 + i] * inv;

    float o0 = B2[0], o1 = B2[1];
    for (int j = 0; j < 64; j++) {
        float h0 = 0.f, h1 = 0.f, h2 = 0.f, h3 = 0.f;
        #pragma unroll
        for (int i = 0; i < 64; i += 4) {
            h0 = fmaf(p[i + 0], W1[(i + 0) * 64 + j], h0);
            h1 = fmaf(p[i + 1], W1[(i + 1) * 64 + j], h1);
            h2 = fmaf(p[i + 2], W1[(i + 2) * 64 + j], h2);
            h3 = fmaf(p[i + 3], W1[(i + 3) * 64 + j], h3);
        }
        const float h = fmaxf((h0 + h1) + (h2 + h3) + B1[j], 0.0f);
        o0 = fmaf(h, W2[j * 2 + 0], o0);
        o1 = fmaf(h, W2[j * 2 + 1], o1);
    }
    out[g * 2 + 0] = o0;
    out[g * 2 + 1] = o1;
}

// ---------------------------------------------------------------------------
// Launch. Inputs (metadata order): x, edge_index, batch,
//   w_rel0, b_rel0, w_root0, w_rel1, b_rel1, w_root1, w_rel2, b_rel2, w_root2,
//   head_w1, head_b1, head_w2, head_b2
// ---------------------------------------------------------------------------
extern "C" void kernel_launch(void* const* d_in, const int* in_sizes, int n_in,
                              void* d_out, int out_size)
{
    const float* x       = (const float*)d_in[0];
    const void*  edges   = d_in[1];
    const void*  batch   = d_in[2];
    const float* w_rel0  = (const float*)d_in[3];
    const float* b_rel0  = (const float*)d_in[4];
    const float* w_root0 = (const float*)d_in[5];
    const float* w_rel1  = (const float*)d_in[6];
    const float* b_rel1  = (const float*)d_in[7];
    const float* w_root1 = (const float*)d_in[8];
    const float* w_rel2  = (const float*)d_in[9];
    const float* b_rel2  = (const float*)d_in[10];
    const float* w_root2 = (const float*)d_in[11];
    const float* hw1     = (const float*)d_in[12];
    const float* hb1     = (const float*)d_in[13];
    const float* hw2     = (const float*)d_in[14];
    const float* hb2     = (const float*)d_in[15];
    float* out = (float*)d_out;

    const int n_edges = in_sizes[1] / 2;

    float *Y, *AA, *AB;
    cudaGetSymbolAddress((void**)&Y,  g_Y);
    cudaGetSymbolAddress((void**)&AA, g_AGG_A);
    cudaGetSymbolAddress((void**)&AB, g_AGG_B);

    const size_t smem0 = (size_t)(2 * 128 * 64 + 128 * 68) * sizeof(float); // 100352
    const size_t smem1 = (size_t)(2 * 64 * 64 + 64 * 68) * sizeof(float);   // 50176
    cudaFuncSetAttribute((const void*)proj_kernel<128, false>,
                         cudaFuncAttributeMaxDynamicSharedMemorySize, (int)smem0);
    cudaFuncSetAttribute((const void*)proj_kernel<64, true>,
                         cudaFuncAttributeMaxDynamicSharedMemorySize, (int)smem1);

    detect_kernel<<<1, 1>>>((const int*)edges);

    const int scatter_grid = (n_edges * 16 + 255) / 256;
    const int pool_grid    = (N_NODES * 16 + 255) / 256;

    // Layer 0: Y = x@Wrel0 ; AGG_A = x@Wroot0 + b0 ; AGG_A[dst] += Y[src]
    proj_kernel<128, false><<<296, 256, smem0>>>(x, w_rel0, w_root0, b_rel0, Y, AA);
    scatter_kernel<<<scatter_grid, 256>>>((const float4*)Y, edges, AA, n_edges);

    // Layer 1 (ReLU fused on read of AGG_A)
    proj_kernel<64, true><<<592, 256, smem1>>>(AA, w_rel1, w_root1, b_rel1, Y, AB);
    scatter_kernel<<<scatter_grid, 256>>>((const float4*)Y, edges, AB, n_edges);

    // Layer 2 (ReLU fused on read of AGG_B)
    proj_kernel<64, true><<<592, 256, smem1>>>(AB, w_rel2, w_root2, b_rel2, Y, AA);
    scatter_kernel<<<scatter_grid, 256>>>((const float4*)Y, edges, AA, n_edges);

    // Mean pool (ReLU fused) + head MLP
    zero_pool_kernel<<<1, 256>>>();
    pool_kernel<<<pool_grid, 256>>>(AA, batch);
    head_kernel<<<1, 64>>>(hw1, hb1, hw2, hb2, out);
}

// round 5
// speedup vs baseline: 1.1326x; 1.1326x over previous
#include <cuda_runtime.h>
#include <cstdint>
#include <cstddef>

#define N_NODES 100000
#define N_GRAPHS 64
#define HIDC 64
#define MAX_EDGES 2000000

// ---------------------------------------------------------------------------
// Scratch (static device globals — no allocation anywhere)
// ---------------------------------------------------------------------------
__device__ float g_Y[(size_t)N_NODES * HIDC];      // x @ w_rel   (25.6 MB)
__device__ float g_AGG_A[(size_t)N_NODES * HIDC];  // ping (25.6 MB)
__device__ float g_AGG_B[(size_t)N_NODES * HIDC];  // pong (25.6 MB)
__device__ float g_sums[N_GRAPHS * HIDC];
__device__ float g_counts[N_GRAPHS];
__device__ int   g_idx64;                          // 1 if indices are int64

// CSR (dst-sorted edge list, rebuilt every call — graph-replay safe)
__device__ int g_deg[N_NODES];
__device__ int g_off[N_NODES + 1];
__device__ int g_cur[N_NODES];
__device__ int g_csr[MAX_EDGES];

// ---------------------------------------------------------------------------
// Helpers
// ---------------------------------------------------------------------------
__device__ __forceinline__ void red_add_f4(float* addr, float4 v) {
    asm volatile("red.global.add.v4.f32 [%0], {%1, %2, %3, %4};"
                 :: "l"(addr), "f"(v.x), "f"(v.y), "f"(v.z), "f"(v.w)
                 : "memory");
}

// Packed f32x2 FMA (Blackwell): one instruction = two fp32 FMAs.
__device__ __forceinline__ unsigned long long pack2(float a, float b) {
    unsigned long long r;
    asm("mov.b64 %0, {%1, %2};" : "=l"(r) : "f"(a), "f"(b));
    return r;
}
__device__ __forceinline__ void fma2(unsigned long long& acc,
                                     unsigned long long a, unsigned long long b) {
    asm("fma.rn.f32x2 %0, %1, %2, %0;" : "+l"(acc) : "l"(a), "l"(b));
}
__device__ __forceinline__ float2 unpack2(unsigned long long v) {
    float2 r;
    asm("mov.b64 {%0, %1}, %2;" : "=f"(r.x), "=f"(r.y) : "l"(v));
    return r;
}

// ---------------------------------------------------------------------------
// Index-dtype detection (int64 nonneg < 2^31 has zero odd words)
// ---------------------------------------------------------------------------
__global__ void detect_kernel(const int* __restrict__ ei) {
    int z = ei[1] | ei[3] | ei[5] | ei[7] | ei[9] | ei[11] | ei[13] | ei[15];
    g_idx64 = (z == 0) ? 1 : 0;
}

// ---------------------------------------------------------------------------
// CSR build: zero -> histogram -> scan (1 block) -> fill
// ---------------------------------------------------------------------------
__global__ void zero_deg_kernel() {
    int i = blockIdx.x * 1024 + threadIdx.x;
    if (i < N_NODES) g_deg[i] = 0;
}

__global__ void hist_kernel(const void* __restrict__ ei, int n_edges) {
    int e = blockIdx.x * 256 + threadIdx.x;
    if (e >= n_edges) return;
    int d = g_idx64 ? (int)((const long long*)ei)[e + n_edges]
                    : ((const int*)ei)[e + n_edges];
    atomicAdd(&g_deg[d], 1);
}

__global__ __launch_bounds__(1024) void scan_kernel() {
    const int T = 1024;
    const int PER = (N_NODES + T - 1) / T;  // 98
    const int t = threadIdx.x;
    const int base = t * PER;

    int s = 0;
    for (int i = 0; i < PER; i++) {
        int n = base + i;
        if (n < N_NODES) s += g_deg[n];
    }
    __shared__ int sm[T];
    sm[t] = s;
    __syncthreads();
    for (int d = 1; d < T; d <<= 1) {
        int v = (t >= d) ? sm[t - d] : 0;
        __syncthreads();
        if (t >= d) sm[t] += v;
        __syncthreads();
    }
    int run = (t == 0) ? 0 : sm[t - 1];
    for (int i = 0; i < PER; i++) {
        int n = base + i;
        if (n < N_NODES) {
            g_off[n] = run;
            g_cur[n] = run;
            run += g_deg[n];
        }
    }
    if (t == T - 1) g_off[N_NODES] = run;
}

__global__ void fill_kernel(const void* __restrict__ ei, int n_edges) {
    int e = blockIdx.x * 256 + threadIdx.x;
    if (e >= n_edges) return;
    int s, d;
    if (g_idx64) {
        const long long* p = (const long long*)ei;
        s = (int)p[e];
        d = (int)p[e + n_edges];
    } else {
        const int* p = (const int*)ei;
        s = p[e];
        d = p[e + n_edges];
    }
    int pos = atomicAdd(&g_cur[d], 1);
    g_csr[pos] = s;
}

// ---------------------------------------------------------------------------
// Fused projection (packed f32x2 FMAs):
//   Y[n]   = act(X[n]) @ Wrel
//   AGG[n] = act(X[n]) @ Wroot + b_rel      (act = ReLU for layers 1,2)
// block = 256 threads, tile = 64 nodes x 64 out-ch;
// thread owns 4 nodes x (2 channel-pairs) x 2 matrices = 16 packed accs.
// ---------------------------------------------------------------------------
template<int IN, bool RELU_IN>
__global__ __launch_bounds__(256)
void proj_kernel(const float* __restrict__ X,
                 const float* __restrict__ Wrel,
                 const float* __restrict__ Wroot,
                 const float* __restrict__ Brel,
                 float* __restrict__ Y,
                 float* __restrict__ AGG)
{
    extern __shared__ float smem[];
    float* wr = smem;                 // IN*64
    float* wo = wr + IN * 64;         // IN*64
    float* xs = wo + IN * 64;         // IN*68 padded, transposed xs[i][node]
    const int XS_STRIDE = 68;

    for (int i = threadIdx.x; i < IN * 64; i += 256) {
        wr[i] = Wrel[i];
        wo[i] = Wroot[i];
    }

    const int tid = threadIdx.x;
    const int chg = tid & 15;   // channel pair-group: channels chg*4 .. chg*4+3
    const int ng  = tid >> 4;   // 4-node group

    const float b0 = Brel[chg * 4 + 0];
    const float b1 = Brel[chg * 4 + 1];
    const float b2 = Brel[chg * 4 + 2];
    const float b3 = Brel[chg * 4 + 3];

    const int n_tiles = (N_NODES + 63) / 64;
    for (int tile = blockIdx.x; tile < n_tiles; tile += gridDim.x) {
        const int base = tile * 64;
        __syncthreads();

        {
            const int node_l = tid >> 2;
            const int part   = tid & 3;
            const int node   = base + node_l;
            const bool valid = node < N_NODES;
            const float* xrow = X + (size_t)node * IN + part * (IN / 4);
            for (int k = 0; k < IN / 4; k++) {
                float v = valid ? xrow[k] : 0.0f;
                if (RELU_IN) v = fmaxf(v, 0.0f);
                xs[(part * (IN / 4) + k) * XS_STRIDE + node_l] = v;
            }
        }
        __syncthreads();

        unsigned long long acc_r[4][2], acc_o[4][2];
        #pragma unroll
        for (int a = 0; a < 4; a++) {
            acc_r[a][0] = 0ULL; acc_r[a][1] = 0ULL;
            acc_o[a][0] = 0ULL; acc_o[a][1] = 0ULL;
        }

        #pragma unroll 4
        for (int i = 0; i < IN; i++) {
            const float4 xv = *(const float4*)(xs + i * XS_STRIDE + (ng << 2));
            const ulonglong2 wrv = *(const ulonglong2*)(wr + (i << 6) + (chg << 2));
            const ulonglong2 wov = *(const ulonglong2*)(wo + (i << 6) + (chg << 2));
            const unsigned long long x0 = pack2(xv.x, xv.x);
            const unsigned long long x1 = pack2(xv.y, xv.y);
            const unsigned long long x2 = pack2(xv.z, xv.z);
            const unsigned long long x3 = pack2(xv.w, xv.w);
            fma2(acc_r[0][0], x0, wrv.x); fma2(acc_r[0][1], x0, wrv.y);
            fma2(acc_o[0][0], x0, wov.x); fma2(acc_o[0][1], x0, wov.y);
            fma2(acc_r[1][0], x1, wrv.x); fma2(acc_r[1][1], x1, wrv.y);
            fma2(acc_o[1][0], x1, wov.x); fma2(acc_o[1][1], x1, wov.y);
            fma2(acc_r[2][0], x2, wrv.x); fma2(acc_r[2][1], x2, wrv.y);
            fma2(acc_o[2][0], x2, wov.x); fma2(acc_o[2][1], x2, wov.y);
            fma2(acc_r[3][0], x3, wrv.x); fma2(acc_r[3][1], x3, wrv.y);
            fma2(acc_o[3][0], x3, wov.x); fma2(acc_o[3][1], x3, wov.y);
        }

        const int node0 = base + ng * 4;
        #pragma unroll
        for (int a = 0; a < 4; a++) {
            const int node = node0 + a;
            if (node < N_NODES) {
                const float2 r01 = unpack2(acc_r[a][0]);
                const float2 r23 = unpack2(acc_r[a][1]);
                const float2 o01 = unpack2(acc_o[a][0]);
                const float2 o23 = unpack2(acc_o[a][1]);
                float* yp = Y   + (size_t)node * 64 + chg * 4;
                float* ap = AGG + (size_t)node * 64 + chg * 4;
                *(float4*)yp = make_float4(r01.x, r01.y, r23.x, r23.y);
                *(float4*)ap = make_float4(o01.x + b0, o01.y + b1,
                                           o23.x + b2, o23.y + b3);
            }
        }
    }
}

// ---------------------------------------------------------------------------
// CSR gather: AGG[dst] += sum_{src in csr[dst]} Y[src]. No atomics.
// 16 lanes per dst node, one float4 channel slice each.
// ---------------------------------------------------------------------------
__global__ __launch_bounds__(256)
void gather_kernel(const float4* __restrict__ Y, float4* __restrict__ AGG)
{
    const int t = blockIdx.x * 256 + threadIdx.x;
    const int node = t >> 4;
    if (node >= N_NODES) return;
    const int q = t & 15;

    int k = g_off[node];
    const int end = g_off[node + 1];
    float4 acc = AGG[(size_t)node * 16 + q];   // root term + bias

    for (; k + 4 <= end; k += 4) {
        const int s0 = g_csr[k + 0];
        const int s1 = g_csr[k + 1];
        const int s2 = g_csr[k + 2];
        const int s3 = g_csr[k + 3];
        const float4 v0 = Y[(size_t)s0 * 16 + q];
        const float4 v1 = Y[(size_t)s1 * 16 + q];
        const float4 v2 = Y[(size_t)s2 * 16 + q];
        const float4 v3 = Y[(size_t)s3 * 16 + q];
        acc.x += (v0.x + v1.x) + (v2.x + v3.x);
        acc.y += (v0.y + v1.y) + (v2.y + v3.y);
        acc.z += (v0.z + v1.z) + (v2.z + v3.z);
        acc.w += (v0.w + v1.w) + (v2.w + v3.w);
    }
    for (; k < end; k++) {
        const int s = g_csr[k];
        const float4 v = Y[(size_t)s * 16 + q];
        acc.x += v.x; acc.y += v.y; acc.z += v.z; acc.w += v.w;
    }
    AGG[(size_t)node * 16 + q] = acc;
}

// ---------------------------------------------------------------------------
// Pool (hierarchical: batch is sorted -> run-length accumulate) + head
// ---------------------------------------------------------------------------
__global__ void zero_pool_kernel() {
    const int t = threadIdx.x;
    for (int i = t; i < N_GRAPHS * HIDC; i += 256) g_sums[i] = 0.0f;
    if (t < N_GRAPHS) g_counts[t] = 0.0f;
}

#define PCHUNK 16
__global__ __launch_bounds__(256)
void pool_kernel(const float* __restrict__ H, const void* __restrict__ batch)
{
    const int t = blockIdx.x * 256 + threadIdx.x;
    const int grp = t >> 4;
    const int q = t & 15;
    const int base = grp * PCHUNK;
    if (base >= N_NODES) return;
    const int end = (base + PCHUNK < N_NODES) ? base + PCHUNK : N_NODES;

    float4 acc = make_float4(0.f, 0.f, 0.f, 0.f);
    float cnt = 0.f;
    int cur = -1;
    for (int n = base; n < end; n++) {
        int g = g_idx64 ? (int)((const long long*)batch)[n]
                        : ((const int*)batch)[n];
        if (g != cur) {
            if (cur >= 0) {
                red_add_f4(g_sums + cur * 64 + q * 4, acc);
                if (q == 0) atomicAdd(&g_counts[cur], cnt);
            }
            acc = make_float4(0.f, 0.f, 0.f, 0.f);
            cnt = 0.f;
            cur = g;
        }
        float4 v = ((const float4*)H)[(size_t)n * 16 + q];
        acc.x += fmaxf(v.x, 0.0f);  // final-layer ReLU fused here
        acc.y += fmaxf(v.y, 0.0f);
        acc.z += fmaxf(v.z, 0.0f);
        acc.w += fmaxf(v.w, 0.0f);
        cnt += 1.0f;
    }
    if (cur >= 0) {
        red_add_f4(g_sums + cur * 64 + q * 4, acc);
        if (q == 0) atomicAdd(&g_counts[cur], cnt);
    }
}

__global__ void head_kernel(const float* __restrict__ W1, const float* __restrict__ B1,
                            const float* __restrict__ W2, const float* __restrict__ B2,
                            float* __restrict__ out)
{
    const int g = threadIdx.x;
    if (g >= N_GRAPHS) return;
    const float inv = 1.0f / fmaxf(g_counts[g], 1.0f);
    float p[64];
    #pragma unroll
    for (int i = 0; i < 64; i++) p[i] = g_sums[g * 64 + i] * inv;

    float o0 = B2[0], o1 = B2[1];
    for (int j = 0; j < 64; j++) {
        float h0 = 0.f, h1 = 0.f, h2 = 0.f, h3 = 0.f;
        #pragma unroll
        for (int i = 0; i < 64; i += 4) {
            h0 = fmaf(p[i + 0], W1[(i + 0) * 64 + j], h0);
            h1 = fmaf(p[i + 1], W1[(i + 1) * 64 + j], h1);
            h2 = fmaf(p[i + 2], W1[(i + 2) * 64 + j], h2);
            h3 = fmaf(p[i + 3], W1[(i + 3) * 64 + j], h3);
        }
        const float h = fmaxf((h0 + h1) + (h2 + h3) + B1[j], 0.0f);
        o0 = fmaf(h, W2[j * 2 + 0], o0);
        o1 = fmaf(h, W2[j * 2 + 1], o1);
    }
    out[g * 2 + 0] = o0;
    out[g * 2 + 1] = o1;
}

// ---------------------------------------------------------------------------
// Launch
// ---------------------------------------------------------------------------
extern "C" void kernel_launch(void* const* d_in, const int* in_sizes, int n_in,
                              void* d_out, int out_size)
{
    const float* x       = (const float*)d_in[0];
    const void*  edges   = d_in[1];
    const void*  batch   = d_in[2];
    const float* w_rel0  = (const float*)d_in[3];
    const float* b_rel0  = (const float*)d_in[4];
    const float* w_root0 = (const float*)d_in[5];
    const float* w_rel1  = (const float*)d_in[6];
    const float* b_rel1  = (const float*)d_in[7];
    const float* w_root1 = (const float*)d_in[8];
    const float* w_rel2  = (const float*)d_in[9];
    const float* b_rel2  = (const float*)d_in[10];
    const float* w_root2 = (const float*)d_in[11];
    const float* hw1     = (const float*)d_in[12];
    const float* hb1     = (const float*)d_in[13];
    const float* hw2     = (const float*)d_in[14];
    const float* hb2     = (const float*)d_in[15];
    float* out = (float*)d_out;

    int n_edges = in_sizes[1] / 2;
    if (n_edges > MAX_EDGES) n_edges = MAX_EDGES;

    float *Y, *AA, *AB;
    cudaGetSymbolAddress((void**)&Y,  g_Y);
    cudaGetSymbolAddress((void**)&AA, g_AGG_A);
    cudaGetSymbolAddress((void**)&AB, g_AGG_B);

    const size_t smem0 = (size_t)(2 * 128 * 64 + 128 * 68) * sizeof(float); // 100352
    const size_t smem1 = (size_t)(2 * 64 * 64 + 64 * 68) * sizeof(float);   // 50176
    cudaFuncSetAttribute((const void*)proj_kernel<128, false>,
                         cudaFuncAttributeMaxDynamicSharedMemorySize, (int)smem0);
    cudaFuncSetAttribute((const void*)proj_kernel<64, true>,
                         cudaFuncAttributeMaxDynamicSharedMemorySize, (int)smem1);

    const int edge_grid   = (n_edges + 255) / 256;
    const int gather_grid = (N_NODES * 16 + 255) / 256;
    const int pool_grid   = ((N_NODES + PCHUNK - 1) / PCHUNK * 16 + 255) / 256;

    // CSR build (edges identical across layers -> build once, use 3x)
    detect_kernel<<<1, 1>>>((const int*)edges);
    zero_deg_kernel<<<(N_NODES + 1023) / 1024, 1024>>>();
    hist_kernel<<<edge_grid, 256>>>(edges, n_edges);
    scan_kernel<<<1, 1024>>>();
    fill_kernel<<<edge_grid, 256>>>(edges, n_edges);

    // Layer 0
    proj_kernel<128, false><<<296, 256, smem0>>>(x, w_rel0, w_root0, b_rel0, Y, AA);
    gather_kernel<<<gather_grid, 256>>>((const float4*)Y, (float4*)AA);

    // Layer 1 (ReLU fused on read)
    proj_kernel<64, true><<<592, 256, smem1>>>(AA, w_rel1, w_root1, b_rel1, Y, AB);
    gather_kernel<<<gather_grid, 256>>>((const float4*)Y, (float4*)AB);

    // Layer 2
    proj_kernel<64, true><<<592, 256, smem1>>>(AB, w_rel2, w_root2, b_rel2, Y, AA);
    gather_kernel<<<gather_grid, 256>>>((const float4*)Y, (float4*)AA);

    // Mean pool (ReLU fused) + head
    zero_pool_kernel<<<1, 256>>>();
    pool_kernel<<<pool_grid, 256>>>(AA, batch);
    head_kernel<<<1, 64>>>(hw1, hb1, hw2, hb2, out);
}

// round 6
// speedup vs baseline: 1.5734x; 1.3893x over previous
#include <cuda_runtime.h>
#include <cstdint>
#include <cstddef>

#define N_NODES 100000
#define N_GRAPHS 64
#define HIDC 64
#define MAX_EDGES 2000000
#define NB 98   // ceil(N_NODES / 1024)

// ---------------------------------------------------------------------------
// Scratch (static device globals — no allocation anywhere)
// ---------------------------------------------------------------------------
__device__ float g_Y[(size_t)N_NODES * HIDC];      // x @ w_rel   (25.6 MB)
__device__ float g_AGG_A[(size_t)N_NODES * HIDC];  // ping (25.6 MB)
__device__ float g_AGG_B[(size_t)N_NODES * HIDC];  // pong (25.6 MB)
__device__ float g_sums[N_GRAPHS * HIDC];
__device__ float g_counts[N_GRAPHS];
__device__ int   g_idx64;                          // 1 if indices are int64

// CSR (dst-sorted edge list, rebuilt every call — graph-replay safe)
__device__ int g_deg[N_NODES];
__device__ int g_off[N_NODES + 1];
__device__ int g_cur[N_NODES];
__device__ int g_csr[MAX_EDGES];
__device__ int g_bsum[NB];

// ---------------------------------------------------------------------------
// Helpers
// ---------------------------------------------------------------------------
__device__ __forceinline__ void red_add_f4(float* addr, float4 v) {
    asm volatile("red.global.add.v4.f32 [%0], {%1, %2, %3, %4};"
                 :: "l"(addr), "f"(v.x), "f"(v.y), "f"(v.z), "f"(v.w)
                 : "memory");
}

// Packed f32x2 FMA (Blackwell): one instruction = two fp32 FMAs.
__device__ __forceinline__ unsigned long long pack2(float a, float b) {
    unsigned long long r;
    asm("mov.b64 %0, {%1, %2};" : "=l"(r) : "f"(a), "f"(b));
    return r;
}
__device__ __forceinline__ void fma2(unsigned long long& acc,
                                     unsigned long long a, unsigned long long b) {
    asm("fma.rn.f32x2 %0, %1, %2, %0;" : "+l"(acc) : "l"(a), "l"(b));
}
__device__ __forceinline__ float2 unpack2(unsigned long long v) {
    float2 r;
    asm("mov.b64 {%0, %1}, %2;" : "=f"(r.x), "=f"(r.y) : "l"(v));
    return r;
}

// ---------------------------------------------------------------------------
// Index-dtype detection (int64 nonneg < 2^31 has zero odd words)
// ---------------------------------------------------------------------------
__global__ void detect_kernel(const int* __restrict__ ei) {
    int z = ei[1] | ei[3] | ei[5] | ei[7] | ei[9] | ei[11] | ei[13] | ei[15];
    g_idx64 = (z == 0) ? 1 : 0;
}

// ---------------------------------------------------------------------------
// CSR build: zero -> histogram -> 3-stage hierarchical scan -> fill
// ---------------------------------------------------------------------------
__global__ void zero_deg_kernel() {
    int i = blockIdx.x * 1024 + threadIdx.x;
    if (i < N_NODES) g_deg[i] = 0;
}

__global__ void hist_kernel(const void* __restrict__ ei, int n_edges) {
    int e = blockIdx.x * 256 + threadIdx.x;
    if (e >= n_edges) return;
    int d = g_idx64 ? (int)((const long long*)ei)[e + n_edges]
                    : ((const int*)ei)[e + n_edges];
    atomicAdd(&g_deg[d], 1);
}

// Stage 1: per-block (1024-node) degree sums.
__global__ __launch_bounds__(1024) void block_reduce_kernel() {
    const int t = threadIdx.x;
    const int n = blockIdx.x * 1024 + t;
    int v = (n < N_NODES) ? g_deg[n] : 0;
    #pragma unroll
    for (int o = 16; o; o >>= 1) v += __shfl_down_sync(0xFFFFFFFFu, v, o);
    __shared__ int ws[32];
    if ((t & 31) == 0) ws[t >> 5] = v;
    __syncthreads();
    if (t < 32) {
        int s = ws[t];
        #pragma unroll
        for (int o = 16; o; o >>= 1) s += __shfl_down_sync(0xFFFFFFFFu, s, o);
        if (t == 0) g_bsum[blockIdx.x] = s;
    }
}

// Stage 2: inclusive scan of the NB block sums (1 block).
__global__ __launch_bounds__(128) void bsum_scan_kernel() {
    __shared__ int sm[NB];
    const int t = threadIdx.x;
    if (t < NB) sm[t] = g_bsum[t];
    __syncthreads();
    for (int d = 1; d < NB; d <<= 1) {
        int v = (t >= d && t < NB) ? sm[t - d] : 0;
        __syncthreads();
        if (t >= d && t < NB) sm[t] += v;
        __syncthreads();
    }
    if (t < NB) g_bsum[t] = sm[t];
    if (t == NB - 1) g_off[N_NODES] = sm[t];
}

// Stage 3: intra-block exclusive scan + block base -> final offsets.
__global__ __launch_bounds__(1024) void offsets_kernel() {
    const int b = blockIdx.x;
    const int t = threadIdx.x;
    const int n = b * 1024 + t;
    const int lane = t & 31, w = t >> 5;
    const int v = (n < N_NODES) ? g_deg[n] : 0;

    int inc = v;
    #pragma unroll
    for (int o = 1; o < 32; o <<= 1) {
        int u = __shfl_up_sync(0xFFFFFFFFu, inc, o);
        if (lane >= o) inc += u;
    }
    __shared__ int ws[32];
    if (lane == 31) ws[w] = inc;
    __syncthreads();
    if (t < 32) {
        int s = ws[t];
        int si = s;
        #pragma unroll
        for (int o = 1; o < 32; o <<= 1) {
            int u = __shfl_up_sync(0xFFFFFFFFu, si, o);
            if (t >= o) si += u;
        }
        ws[t] = si - s;   // exclusive warp base
    }
    __syncthreads();
    const int base = (b ? g_bsum[b - 1] : 0) + ws[w] + (inc - v);
    if (n < N_NODES) { g_off[n] = base; g_cur[n] = base; }
}

__global__ void fill_kernel(const void* __restrict__ ei, int n_edges) {
    int e = blockIdx.x * 256 + threadIdx.x;
    if (e >= n_edges) return;
    int s, d;
    if (g_idx64) {
        const long long* p = (const long long*)ei;
        s = (int)p[e];
        d = (int)p[e + n_edges];
    } else {
        const int* p = (const int*)ei;
        s = p[e];
        d = p[e + n_edges];
    }
    int pos = atomicAdd(&g_cur[d], 1);
    g_csr[pos] = s;
}

// ---------------------------------------------------------------------------
// Fused projection (packed f32x2 FMAs):
//   Y[n]   = act(X[n]) @ Wrel
//   AGG[n] = act(X[n]) @ Wroot + b_rel      (act = ReLU for layers 1,2)
// ---------------------------------------------------------------------------
template<int IN, bool RELU_IN>
__global__ __launch_bounds__(256)
void proj_kernel(const float* __restrict__ X,
                 const float* __restrict__ Wrel,
                 const float* __restrict__ Wroot,
                 const float* __restrict__ Brel,
                 float* __restrict__ Y,
                 float* __restrict__ AGG)
{
    extern __shared__ float smem[];
    float* wr = smem;                 // IN*64
    float* wo = wr + IN * 64;         // IN*64
    float* xs = wo + IN * 64;         // IN*68 padded, transposed xs[i][node]
    const int XS_STRIDE = 68;

    for (int i = threadIdx.x; i < IN * 64; i += 256) {
        wr[i] = Wrel[i];
        wo[i] = Wroot[i];
    }

    const int tid = threadIdx.x;
    const int chg = tid & 15;
    const int ng  = tid >> 4;

    const float b0 = Brel[chg * 4 + 0];
    const float b1 = Brel[chg * 4 + 1];
    const float b2 = Brel[chg * 4 + 2];
    const float b3 = Brel[chg * 4 + 3];

    const int n_tiles = (N_NODES + 63) / 64;
    for (int tile = blockIdx.x; tile < n_tiles; tile += gridDim.x) {
        const int base = tile * 64;
        __syncthreads();

        {
            const int node_l = tid >> 2;
            const int part   = tid & 3;
            const int node   = base + node_l;
            const bool valid = node < N_NODES;
            const float* xrow = X + (size_t)node * IN + part * (IN / 4);
            for (int k = 0; k < IN / 4; k++) {
                float v = valid ? xrow[k] : 0.0f;
                if (RELU_IN) v = fmaxf(v, 0.0f);
                xs[(part * (IN / 4) + k) * XS_STRIDE + node_l] = v;
            }
        }
        __syncthreads();

        unsigned long long acc_r[4][2], acc_o[4][2];
        #pragma unroll
        for (int a = 0; a < 4; a++) {
            acc_r[a][0] = 0ULL; acc_r[a][1] = 0ULL;
            acc_o[a][0] = 0ULL; acc_o[a][1] = 0ULL;
        }

        #pragma unroll 4
        for (int i = 0; i < IN; i++) {
            const float4 xv = *(const float4*)(xs + i * XS_STRIDE + (ng << 2));
            const ulonglong2 wrv = *(const ulonglong2*)(wr + (i << 6) + (chg << 2));
            const ulonglong2 wov = *(const ulonglong2*)(wo + (i << 6) + (chg << 2));
            const unsigned long long x0 = pack2(xv.x, xv.x);
            const unsigned long long x1 = pack2(xv.y, xv.y);
            const unsigned long long x2 = pack2(xv.z, xv.z);
            const unsigned long long x3 = pack2(xv.w, xv.w);
            fma2(acc_r[0][0], x0, wrv.x); fma2(acc_r[0][1], x0, wrv.y);
            fma2(acc_o[0][0], x0, wov.x); fma2(acc_o[0][1], x0, wov.y);
            fma2(acc_r[1][0], x1, wrv.x); fma2(acc_r[1][1], x1, wrv.y);
            fma2(acc_o[1][0], x1, wov.x); fma2(acc_o[1][1], x1, wov.y);
            fma2(acc_r[2][0], x2, wrv.x); fma2(acc_r[2][1], x2, wrv.y);
            fma2(acc_o[2][0], x2, wov.x); fma2(acc_o[2][1], x2, wov.y);
            fma2(acc_r[3][0], x3, wrv.x); fma2(acc_r[3][1], x3, wrv.y);
            fma2(acc_o[3][0], x3, wov.x); fma2(acc_o[3][1], x3, wov.y);
        }

        const int node0 = base + ng * 4;
        #pragma unroll
        for (int a = 0; a < 4; a++) {
            const int node = node0 + a;
            if (node < N_NODES) {
                const float2 r01 = unpack2(acc_r[a][0]);
                const float2 r23 = unpack2(acc_r[a][1]);
                const float2 o01 = unpack2(acc_o[a][0]);
                const float2 o23 = unpack2(acc_o[a][1]);
                float* yp = Y   + (size_t)node * 64 + chg * 4;
                float* ap = AGG + (size_t)node * 64 + chg * 4;
                *(float4*)yp = make_float4(r01.x, r01.y, r23.x, r23.y);
                *(float4*)ap = make_float4(o01.x + b0, o01.y + b1,
                                           o23.x + b2, o23.y + b3);
            }
        }
    }
}

// ---------------------------------------------------------------------------
// CSR gather: AGG[dst] += sum_{src in csr[dst]} Y[src]. No atomics.
// ---------------------------------------------------------------------------
__global__ __launch_bounds__(256)
void gather_kernel(const float4* __restrict__ Y, float4* __restrict__ AGG)
{
    const int t = blockIdx.x * 256 + threadIdx.x;
    const int node = t >> 4;
    if (node >= N_NODES) return;
    const int q = t & 15;

    int k = g_off[node];
    const int end = g_off[node + 1];
    float4 acc = AGG[(size_t)node * 16 + q];   // root term + bias

    for (; k + 4 <= end; k += 4) {
        const int s0 = g_csr[k + 0];
        const int s1 = g_csr[k + 1];
        const int s2 = g_csr[k + 2];
        const int s3 = g_csr[k + 3];
        const float4 v0 = Y[(size_t)s0 * 16 + q];
        const float4 v1 = Y[(size_t)s1 * 16 + q];
        const float4 v2 = Y[(size_t)s2 * 16 + q];
        const float4 v3 = Y[(size_t)s3 * 16 + q];
        acc.x += (v0.x + v1.x) + (v2.x + v3.x);
        acc.y += (v0.y + v1.y) + (v2.y + v3.y);
        acc.z += (v0.z + v1.z) + (v2.z + v3.z);
        acc.w += (v0.w + v1.w) + (v2.w + v3.w);
    }
    for (; k < end; k++) {
        const int s = g_csr[k];
        const float4 v = Y[(size_t)s * 16 + q];
        acc.x += v.x; acc.y += v.y; acc.z += v.z; acc.w += v.w;
    }
    AGG[(size_t)node * 16 + q] = acc;
}

// ---------------------------------------------------------------------------
// Pool (run-length accumulate over sorted batch) + head
// ---------------------------------------------------------------------------
__global__ void zero_pool_kernel() {
    const int t = threadIdx.x;
    for (int i = t; i < N_GRAPHS * HIDC; i += 256) g_sums[i] = 0.0f;
    if (t < N_GRAPHS) g_counts[t] = 0.0f;
}

#define PCHUNK 16
__global__ __launch_bounds__(256)
void pool_kernel(const float* __restrict__ H, const void* __restrict__ batch)
{
    const int t = blockIdx.x * 256 + threadIdx.x;
    const int grp = t >> 4;
    const int q = t & 15;
    const int base = grp * PCHUNK;
    if (base >= N_NODES) return;
    const int end = (base + PCHUNK < N_NODES) ? base + PCHUNK : N_NODES;

    float4 acc = make_float4(0.f, 0.f, 0.f, 0.f);
    float cnt = 0.f;
    int cur = -1;
    for (int n = base; n < end; n++) {
        int g = g_idx64 ? (int)((const long long*)batch)[n]
                        : ((const int*)batch)[n];
        if (g != cur) {
            if (cur >= 0) {
                red_add_f4(g_sums + cur * 64 + q * 4, acc);
                if (q == 0) atomicAdd(&g_counts[cur], cnt);
            }
            acc = make_float4(0.f, 0.f, 0.f, 0.f);
            cnt = 0.f;
            cur = g;
        }
        float4 v = ((const float4*)H)[(size_t)n * 16 + q];
        acc.x += fmaxf(v.x, 0.0f);
        acc.y += fmaxf(v.y, 0.0f);
        acc.z += fmaxf(v.z, 0.0f);
        acc.w += fmaxf(v.w, 0.0f);
        cnt += 1.0f;
    }
    if (cur >= 0) {
        red_add_f4(g_sums + cur * 64 + q * 4, acc);
        if (q == 0) atomicAdd(&g_counts[cur], cnt);
    }
}

__global__ void head_kernel(const float* __restrict__ W1, const float* __restrict__ B1,
                            const float* __restrict__ W2, const float* __restrict__ B2,
                            float* __restrict__ out)
{
    const int g = threadIdx.x;
    if (g >= N_GRAPHS) return;
    const float inv = 1.0f / fmaxf(g_counts[g], 1.0f);
    float p[64];
    #pragma unroll
    for (int i = 0; i < 64; i++) p[i] = g_sums[g * 64 + i] * inv;

    float o0 = B2[0], o1 = B2[1];
    for (int j = 0; j < 64; j++) {
        float h0 = 0.f, h1 = 0.f, h2 = 0.f, h3 = 0.f;
        #pragma unroll
        for (int i = 0; i < 64; i += 4) {
            h0 = fmaf(p[i + 0], W1[(i + 0) * 64 + j], h0);
            h1 = fmaf(p[i + 1], W1[(i + 1) * 64 + j], h1);
            h2 = fmaf(p[i + 2], W1[(i + 2) * 64 + j], h2);
            h3 = fmaf(p[i + 3], W1[(i + 3) * 64 + j], h3);
        }
        const float h = fmaxf((h0 + h1) + (h2 + h3) + B1[j], 0.0f);
        o0 = fmaf(h, W2[j * 2 + 0], o0);
        o1 = fmaf(h, W2[j * 2 + 1], o1);
    }
    out[g * 2 + 0] = o0;
    out[g * 2 + 1] = o1;
}

// ---------------------------------------------------------------------------
// Launch
// ---------------------------------------------------------------------------
extern "C" void kernel_launch(void* const* d_in, const int* in_sizes, int n_in,
                              void* d_out, int out_size)
{
    const float* x       = (const float*)d_in[0];
    const void*  edges   = d_in[1];
    const void*  batch   = d_in[2];
    const float* w_rel0  = (const float*)d_in[3];
    const float* b_rel0  = (const float*)d_in[4];
    const float* w_root0 = (const float*)d_in[5];
    const float* w_rel1  = (const float*)d_in[6];
    const float* b_rel1  = (const float*)d_in[7];
    const float* w_root1 = (const float*)d_in[8];
    const float* w_rel2  = (const float*)d_in[9];
    const float* b_rel2  = (const float*)d_in[10];
    const float* w_root2 = (const float*)d_in[11];
    const float* hw1     = (const float*)d_in[12];
    const float* hb1     = (const float*)d_in[13];
    const float* hw2     = (const float*)d_in[14];
    const float* hb2     = (const float*)d_in[15];
    float* out = (float*)d_out;

    int n_edges = in_sizes[1] / 2;
    if (n_edges > MAX_EDGES) n_edges = MAX_EDGES;

    float *Y, *AA, *AB;
    cudaGetSymbolAddress((void**)&Y,  g_Y);
    cudaGetSymbolAddress((void**)&AA, g_AGG_A);
    cudaGetSymbolAddress((void**)&AB, g_AGG_B);

    const size_t smem0 = (size_t)(2 * 128 * 64 + 128 * 68) * sizeof(float); // 100352
    const size_t smem1 = (size_t)(2 * 64 * 64 + 64 * 68) * sizeof(float);   // 50176
    cudaFuncSetAttribute((const void*)proj_kernel<128, false>,
                         cudaFuncAttributeMaxDynamicSharedMemorySize, (int)smem0);
    cudaFuncSetAttribute((const void*)proj_kernel<64, true>,
                         cudaFuncAttributeMaxDynamicSharedMemorySize, (int)smem1);

    const int edge_grid   = (n_edges + 255) / 256;
    const int gather_grid = (N_NODES * 16 + 255) / 256;
    const int pool_grid   = ((N_NODES + PCHUNK - 1) / PCHUNK * 16 + 255) / 256;

    // CSR build (edges identical across layers -> build once, use 3x)
    detect_kernel<<<1, 1>>>((const int*)edges);
    zero_deg_kernel<<<NB, 1024>>>();
    hist_kernel<<<edge_grid, 256>>>(edges, n_edges);
    block_reduce_kernel<<<NB, 1024>>>();
    bsum_scan_kernel<<<1, 128>>>();
    offsets_kernel<<<NB, 1024>>>();
    fill_kernel<<<edge_grid, 256>>>(edges, n_edges);

    // Layer 0
    proj_kernel<128, false><<<296, 256, smem0>>>(x, w_rel0, w_root0, b_rel0, Y, AA);
    gather_kernel<<<gather_grid, 256>>>((const float4*)Y, (float4*)AA);

    // Layer 1 (ReLU fused on read)
    proj_kernel<64, true><<<592, 256, smem1>>>(AA, w_rel1, w_root1, b_rel1, Y, AB);
    gather_kernel<<<gather_grid, 256>>>((const float4*)Y, (float4*)AB);

    // Layer 2
    proj_kernel<64, true><<<592, 256, smem1>>>(AB, w_rel2, w_root2, b_rel2, Y, AA);
    gather_kernel<<<gather_grid, 256>>>((const float4*)Y, (float4*)AA);

    // Mean pool (ReLU fused) + head
    zero_pool_kernel<<<1, 256>>>();
    pool_kernel<<<pool_grid, 256>>>(AA, batch);
    head_kernel<<<1, 64>>>(hw1, hb1, hw2, hb2, out);
}

// round 7
// speedup vs baseline: 1.8412x; 1.1702x over previous
#include <cuda_runtime.h>
#include <cstdint>
#include <cstddef>

#define N_NODES 100000
#define N_GRAPHS 64
#define HIDC 64
#define MAX_EDGES 2000000
#define NB 98   // ceil(N_NODES / 1024)

// ---------------------------------------------------------------------------
// Scratch (static device globals — no allocation anywhere)
// ---------------------------------------------------------------------------
__device__ float g_Y[(size_t)N_NODES * HIDC];      // x @ w_rel   (25.6 MB)
__device__ float g_AGG_A[(size_t)N_NODES * HIDC];  // ping (25.6 MB)
__device__ float g_AGG_B[(size_t)N_NODES * HIDC];  // pong (25.6 MB)
__device__ float g_sums[N_GRAPHS * HIDC];
__device__ float g_counts[N_GRAPHS];
__device__ int   g_idx64;                          // 1 if indices are int64

// CSR (dst-sorted edge list, rebuilt every call — graph-replay safe)
__device__ int g_deg[N_NODES];
__device__ int g_off[N_NODES + 1];
__device__ int g_cur[N_NODES];
__device__ int g_csr[MAX_EDGES];
__device__ int g_bsum[NB];

// ---------------------------------------------------------------------------
// Helpers
// ---------------------------------------------------------------------------
__device__ __forceinline__ void red_add_f4(float* addr, float4 v) {
    asm volatile("red.global.add.v4.f32 [%0], {%1, %2, %3, %4};"
                 :: "l"(addr), "f"(v.x), "f"(v.y), "f"(v.z), "f"(v.w)
                 : "memory");
}

// Packed f32x2 FMA (Blackwell): one instruction = two fp32 FMAs.
__device__ __forceinline__ unsigned long long pack2(float a, float b) {
    unsigned long long r;
    asm("mov.b64 %0, {%1, %2};" : "=l"(r) : "f"(a), "f"(b));
    return r;
}
__device__ __forceinline__ void fma2(unsigned long long& acc,
                                     unsigned long long a, unsigned long long b) {
    asm("fma.rn.f32x2 %0, %1, %2, %0;" : "+l"(acc) : "l"(a), "l"(b));
}
__device__ __forceinline__ float2 unpack2(unsigned long long v) {
    float2 r;
    asm("mov.b64 {%0, %1}, %2;" : "=f"(r.x), "=f"(r.y) : "l"(v));
    return r;
}

// ---------------------------------------------------------------------------
// Init: zero degrees + zero pool accumulators + index-dtype detect.
// (int64 nonneg < 2^31 has zero odd 32-bit words)
// ---------------------------------------------------------------------------
__global__ __launch_bounds__(1024) void init_kernel(const int* __restrict__ ei) {
    const int i = blockIdx.x * 1024 + threadIdx.x;
    if (i < N_NODES) g_deg[i] = 0;
    if (blockIdx.x == 0) {
        for (int j = threadIdx.x; j < N_GRAPHS * HIDC; j += 1024) g_sums[j] = 0.0f;
        if (threadIdx.x < N_GRAPHS) g_counts[threadIdx.x] = 0.0f;
        if (threadIdx.x == 0) {
            int z = ei[1] | ei[3] | ei[5] | ei[7] | ei[9] | ei[11] | ei[13] | ei[15];
            g_idx64 = (z == 0) ? 1 : 0;
        }
    }
}

__global__ void hist_kernel(const void* __restrict__ ei, int n_edges) {
    int e = blockIdx.x * 256 + threadIdx.x;
    if (e >= n_edges) return;
    int d = g_idx64 ? (int)((const long long*)ei)[e + n_edges]
                    : ((const int*)ei)[e + n_edges];
    atomicAdd(&g_deg[d], 1);
}

// Stage 1: per-block (1024-node) degree sums.
__global__ __launch_bounds__(1024) void block_reduce_kernel() {
    const int t = threadIdx.x;
    const int n = blockIdx.x * 1024 + t;
    int v = (n < N_NODES) ? g_deg[n] : 0;
    #pragma unroll
    for (int o = 16; o; o >>= 1) v += __shfl_down_sync(0xFFFFFFFFu, v, o);
    __shared__ int ws[32];
    if ((t & 31) == 0) ws[t >> 5] = v;
    __syncthreads();
    if (t < 32) {
        int s = ws[t];
        #pragma unroll
        for (int o = 16; o; o >>= 1) s += __shfl_down_sync(0xFFFFFFFFu, s, o);
        if (t == 0) g_bsum[blockIdx.x] = s;
    }
}

// Stage 2: inclusive scan of the NB block sums (1 block).
__global__ __launch_bounds__(128) void bsum_scan_kernel() {
    __shared__ int sm[NB];
    const int t = threadIdx.x;
    if (t < NB) sm[t] = g_bsum[t];
    __syncthreads();
    for (int d = 1; d < NB; d <<= 1) {
        int v = (t >= d && t < NB) ? sm[t - d] : 0;
        __syncthreads();
        if (t >= d && t < NB) sm[t] += v;
        __syncthreads();
    }
    if (t < NB) g_bsum[t] = sm[t];
    if (t == NB - 1) g_off[N_NODES] = sm[t];
}

// Stage 3: intra-block exclusive scan + block base -> final offsets.
__global__ __launch_bounds__(1024) void offsets_kernel() {
    const int b = blockIdx.x;
    const int t = threadIdx.x;
    const int n = b * 1024 + t;
    const int lane = t & 31, w = t >> 5;
    const int v = (n < N_NODES) ? g_deg[n] : 0;

    int inc = v;
    #pragma unroll
    for (int o = 1; o < 32; o <<= 1) {
        int u = __shfl_up_sync(0xFFFFFFFFu, inc, o);
        if (lane >= o) inc += u;
    }
    __shared__ int ws[32];
    if (lane == 31) ws[w] = inc;
    __syncthreads();
    if (t < 32) {
        int s = ws[t];
        int si = s;
        #pragma unroll
        for (int o = 1; o < 32; o <<= 1) {
            int u = __shfl_up_sync(0xFFFFFFFFu, si, o);
            if (t >= o) si += u;
        }
        ws[t] = si - s;   // exclusive warp base
    }
    __syncthreads();
    const int base = (b ? g_bsum[b - 1] : 0) + ws[w] + (inc - v);
    if (n < N_NODES) { g_off[n] = base; g_cur[n] = base; }
}

__global__ void fill_kernel(const void* __restrict__ ei, int n_edges) {
    int e = blockIdx.x * 256 + threadIdx.x;
    if (e >= n_edges) return;
    int s, d;
    if (g_idx64) {
        const long long* p = (const long long*)ei;
        s = (int)p[e];
        d = (int)p[e + n_edges];
    } else {
        const int* p = (const int*)ei;
        s = p[e];
        d = p[e + n_edges];
    }
    int pos = atomicAdd(&g_cur[d], 1);
    g_csr[pos] = s;
}

// ---------------------------------------------------------------------------
// Fused projection (packed f32x2 FMAs):
//   Y[n]   = act(X[n]) @ Wrel
//   AGG[n] = act(X[n]) @ Wroot + b_rel      (act = ReLU for layers 1,2)
// ---------------------------------------------------------------------------
template<int IN, bool RELU_IN>
__global__ __launch_bounds__(256)
void proj_kernel(const float* __restrict__ X,
                 const float* __restrict__ Wrel,
                 const float* __restrict__ Wroot,
                 const float* __restrict__ Brel,
                 float* __restrict__ Y,
                 float* __restrict__ AGG)
{
    extern __shared__ float smem[];
    float* wr = smem;                 // IN*64
    float* wo = wr + IN * 64;         // IN*64
    float* xs = wo + IN * 64;         // IN*68 padded, transposed xs[i][node]
    const int XS_STRIDE = 68;

    for (int i = threadIdx.x; i < IN * 64; i += 256) {
        wr[i] = Wrel[i];
        wo[i] = Wroot[i];
    }

    const int tid = threadIdx.x;
    const int chg = tid & 15;
    const int ng  = tid >> 4;

    const float b0 = Brel[chg * 4 + 0];
    const float b1 = Brel[chg * 4 + 1];
    const float b2 = Brel[chg * 4 + 2];
    const float b3 = Brel[chg * 4 + 3];

    const int n_tiles = (N_NODES + 63) / 64;
    for (int tile = blockIdx.x; tile < n_tiles; tile += gridDim.x) {
        const int base = tile * 64;
        __syncthreads();

        // Load 64 rows of X transposed into xs. Coalesced float4 LDGs:
        // 4 threads per node, each owns a contiguous IN/4-float chunk.
        {
            const int node_l = tid >> 2;
            const int part   = tid & 3;
            const int node   = base + node_l;
            const bool valid = node < N_NODES;
            const float4* xr4 = (const float4*)(X + (size_t)node * IN + part * (IN / 4));
            #pragma unroll
            for (int k4 = 0; k4 < IN / 16; k4++) {
                float4 v = valid ? xr4[k4] : make_float4(0.f, 0.f, 0.f, 0.f);
                if (RELU_IN) {
                    v.x = fmaxf(v.x, 0.0f); v.y = fmaxf(v.y, 0.0f);
                    v.z = fmaxf(v.z, 0.0f); v.w = fmaxf(v.w, 0.0f);
                }
                const int row = part * (IN / 4) + k4 * 4;
                xs[(row + 0) * XS_STRIDE + node_l] = v.x;
                xs[(row + 1) * XS_STRIDE + node_l] = v.y;
                xs[(row + 2) * XS_STRIDE + node_l] = v.z;
                xs[(row + 3) * XS_STRIDE + node_l] = v.w;
            }
        }
        __syncthreads();

        unsigned long long acc_r[4][2], acc_o[4][2];
        #pragma unroll
        for (int a = 0; a < 4; a++) {
            acc_r[a][0] = 0ULL; acc_r[a][1] = 0ULL;
            acc_o[a][0] = 0ULL; acc_o[a][1] = 0ULL;
        }

        #pragma unroll 4
        for (int i = 0; i < IN; i++) {
            const float4 xv = *(const float4*)(xs + i * XS_STRIDE + (ng << 2));
            const ulonglong2 wrv = *(const ulonglong2*)(wr + (i << 6) + (chg << 2));
            const ulonglong2 wov = *(const ulonglong2*)(wo + (i << 6) + (chg << 2));
            const unsigned long long x0 = pack2(xv.x, xv.x);
            const unsigned long long x1 = pack2(xv.y, xv.y);
            const unsigned long long x2 = pack2(xv.z, xv.z);
            const unsigned long long x3 = pack2(xv.w, xv.w);
            fma2(acc_r[0][0], x0, wrv.x); fma2(acc_r[0][1], x0, wrv.y);
            fma2(acc_o[0][0], x0, wov.x); fma2(acc_o[0][1], x0, wov.y);
            fma2(acc_r[1][0], x1, wrv.x); fma2(acc_r[1][1], x1, wrv.y);
            fma2(acc_o[1][0], x1, wov.x); fma2(acc_o[1][1], x1, wov.y);
            fma2(acc_r[2][0], x2, wrv.x); fma2(acc_r[2][1], x2, wrv.y);
            fma2(acc_o[2][0], x2, wov.x); fma2(acc_o[2][1], x2, wov.y);
            fma2(acc_r[3][0], x3, wrv.x); fma2(acc_r[3][1], x3, wrv.y);
            fma2(acc_o[3][0], x3, wov.x); fma2(acc_o[3][1], x3, wov.y);
        }

        const int node0 = base + ng * 4;
        #pragma unroll
        for (int a = 0; a < 4; a++) {
            const int node = node0 + a;
            if (node < N_NODES) {
                const float2 r01 = unpack2(acc_r[a][0]);
                const float2 r23 = unpack2(acc_r[a][1]);
                const float2 o01 = unpack2(acc_o[a][0]);
                const float2 o23 = unpack2(acc_o[a][1]);
                float* yp = Y   + (size_t)node * 64 + chg * 4;
                float* ap = AGG + (size_t)node * 64 + chg * 4;
                *(float4*)yp = make_float4(r01.x, r01.y, r23.x, r23.y);
                *(float4*)ap = make_float4(o01.x + b0, o01.y + b1,
                                           o23.x + b2, o23.y + b3);
            }
        }
    }
}

// ---------------------------------------------------------------------------
// CSR gather: AGG[dst] += sum_{src in csr[dst]} Y[src]. No atomics.
// ---------------------------------------------------------------------------
__global__ __launch_bounds__(256)
void gather_kernel(const float4* __restrict__ Y, float4* __restrict__ AGG)
{
    const int t = blockIdx.x * 256 + threadIdx.x;
    const int node = t >> 4;
    if (node >= N_NODES) return;
    const int q = t & 15;

    int k = g_off[node];
    const int end = g_off[node + 1];
    float4 acc = AGG[(size_t)node * 16 + q];   // root term + bias

    for (; k + 4 <= end; k += 4) {
        const int s0 = g_csr[k + 0];
        const int s1 = g_csr[k + 1];
        const int s2 = g_csr[k + 2];
        const int s3 = g_csr[k + 3];
        const float4 v0 = Y[(size_t)s0 * 16 + q];
        const float4 v1 = Y[(size_t)s1 * 16 + q];
        const float4 v2 = Y[(size_t)s2 * 16 + q];
        const float4 v3 = Y[(size_t)s3 * 16 + q];
        acc.x += (v0.x + v1.x) + (v2.x + v3.x);
        acc.y += (v0.y + v1.y) + (v2.y + v3.y);
        acc.z += (v0.z + v1.z) + (v2.z + v3.z);
        acc.w += (v0.w + v1.w) + (v2.w + v3.w);
    }
    for (; k < end; k++) {
        const int s = g_csr[k];
        const float4 v = Y[(size_t)s * 16 + q];
        acc.x += v.x; acc.y += v.y; acc.z += v.z; acc.w += v.w;
    }
    AGG[(size_t)node * 16 + q] = acc;
}

// ---------------------------------------------------------------------------
// Pool (run-length accumulate over sorted batch) + head
// ---------------------------------------------------------------------------
#define PCHUNK 16
__global__ __launch_bounds__(256)
void pool_kernel(const float* __restrict__ H, const void* __restrict__ batch)
{
    const int t = blockIdx.x * 256 + threadIdx.x;
    const int grp = t >> 4;
    const int q = t & 15;
    const int base = grp * PCHUNK;
    if (base >= N_NODES) return;
    const int end = (base + PCHUNK < N_NODES) ? base + PCHUNK : N_NODES;

    float4 acc = make_float4(0.f, 0.f, 0.f, 0.f);
    float cnt = 0.f;
    int cur = -1;
    for (int n = base; n < end; n++) {
        int g = g_idx64 ? (int)((const long long*)batch)[n]
                        : ((const int*)batch)[n];
        if (g != cur) {
            if (cur >= 0) {
                red_add_f4(g_sums + cur * 64 + q * 4, acc);
                if (q == 0) atomicAdd(&g_counts[cur], cnt);
            }
            acc = make_float4(0.f, 0.f, 0.f, 0.f);
            cnt = 0.f;
            cur = g;
        }
        float4 v = ((const float4*)H)[(size_t)n * 16 + q];
        acc.x += fmaxf(v.x, 0.0f);
        acc.y += fmaxf(v.y, 0.0f);
        acc.z += fmaxf(v.z, 0.0f);
        acc.w += fmaxf(v.w, 0.0f);
        cnt += 1.0f;
    }
    if (cur >= 0) {
        red_add_f4(g_sums + cur * 64 + q * 4, acc);
        if (q == 0) atomicAdd(&g_counts[cur], cnt);
    }
}

__global__ void head_kernel(const float* __restrict__ W1, const float* __restrict__ B1,
                            const float* __restrict__ W2, const float* __restrict__ B2,
                            float* __restrict__ out)
{
    const int g = threadIdx.x;
    if (g >= N_GRAPHS) return;
    const float inv = 1.0f / fmaxf(g_counts[g], 1.0f);
    float p[64];
    #pragma unroll
    for (int i = 0; i < 64; i++) p[i] = g_sums[g * 64 + i] * inv;

    float o0 = B2[0], o1 = B2[1];
    for (int j = 0; j < 64; j++) {
        float h0 = 0.f, h1 = 0.f, h2 = 0.f, h3 = 0.f;
        #pragma unroll
        for (int i = 0; i < 64; i += 4) {
            h0 = fmaf(p[i + 0], W1[(i + 0) * 64 + j], h0);
            h1 = fmaf(p[i + 1], W1[(i + 1) * 64 + j], h1);
            h2 = fmaf(p[i + 2], W1[(i + 2) * 64 + j], h2);
            h3 = fmaf(p[i + 3], W1[(i + 3) * 64 + j], h3);
        }
        const float h = fmaxf((h0 + h1) + (h2 + h3) + B1[j], 0.0f);
        o0 = fmaf(h, W2[j * 2 + 0], o0);
        o1 = fmaf(h, W2[j * 2 + 1], o1);
    }
    out[g * 2 + 0] = o0;
    out[g * 2 + 1] = o1;
}

// ---------------------------------------------------------------------------
// Launch. CSR build runs on a side stream, overlapped with proj0 (the build
// depends only on edge_index; proj0 only on x + weights). Event fork/join is
// the documented cross-stream graph-capture pattern.
// ---------------------------------------------------------------------------
extern "C" void kernel_launch(void* const* d_in, const int* in_sizes, int n_in,
                              void* d_out, int out_size)
{
    const float* x       = (const float*)d_in[0];
    const void*  edges   = d_in[1];
    const void*  batch   = d_in[2];
    const float* w_rel0  = (const float*)d_in[3];
    const float* b_rel0  = (const float*)d_in[4];
    const float* w_root0 = (const float*)d_in[5];
    const float* w_rel1  = (const float*)d_in[6];
    const float* b_rel1  = (const float*)d_in[7];
    const float* w_root1 = (const float*)d_in[8];
    const float* w_rel2  = (const float*)d_in[9];
    const float* b_rel2  = (const float*)d_in[10];
    const float* w_root2 = (const float*)d_in[11];
    const float* hw1     = (const float*)d_in[12];
    const float* hb1     = (const float*)d_in[13];
    const float* hw2     = (const float*)d_in[14];
    const float* hb2     = (const float*)d_in[15];
    float* out = (float*)d_out;

    int n_edges = in_sizes[1] / 2;
    if (n_edges > MAX_EDGES) n_edges = MAX_EDGES;

    float *Y, *AA, *AB;
    cudaGetSymbolAddress((void**)&Y,  g_Y);
    cudaGetSymbolAddress((void**)&AA, g_AGG_A);
    cudaGetSymbolAddress((void**)&AB, g_AGG_B);

    const size_t smem0 = (size_t)(2 * 128 * 64 + 128 * 68) * sizeof(float); // 100352
    const size_t smem1 = (size_t)(2 * 64 * 64 + 64 * 68) * sizeof(float);   // 50176
    cudaFuncSetAttribute((const void*)proj_kernel<128, false>,
                         cudaFuncAttributeMaxDynamicSharedMemorySize, (int)smem0);
    cudaFuncSetAttribute((const void*)proj_kernel<64, true>,
                         cudaFuncAttributeMaxDynamicSharedMemorySize, (int)smem1);

    // One-time side-stream / event handles (host resources only; the captured
    // work graph is identical on every call). Fallback: if creation fails the
    // handles stay 0 and everything serializes on the default stream.
    static cudaStream_t s2 = 0;
    static cudaEvent_t  evF = 0, evJ = 0;
    static int shandles = 0;
    if (!shandles) {
        shandles = 1;
        cudaStreamCreateWithFlags(&s2, cudaStreamNonBlocking);
        cudaEventCreateWithFlags(&evF, cudaEventDisableTiming);
        cudaEventCreateWithFlags(&evJ, cudaEventDisableTiming);
    }

    const int edge_grid   = (n_edges + 255) / 256;
    const int gather_grid = (N_NODES * 16 + 255) / 256;
    const int pool_grid   = ((N_NODES + PCHUNK - 1) / PCHUNK * 16 + 255) / 256;

    const bool fork = (s2 != 0 && evF != 0 && evJ != 0);
    cudaStream_t sb = fork ? s2 : (cudaStream_t)0;

    // Fork: CSR build on side stream (overlaps proj0 on default stream)
    if (fork) {
        cudaEventRecord(evF, 0);
        cudaStreamWaitEvent(s2, evF, 0);
    }
    init_kernel<<<NB, 1024, 0, sb>>>((const int*)edges);
    hist_kernel<<<edge_grid, 256, 0, sb>>>(edges, n_edges);
    block_reduce_kernel<<<NB, 1024, 0, sb>>>();
    bsum_scan_kernel<<<1, 128, 0, sb>>>();
    offsets_kernel<<<NB, 1024, 0, sb>>>();
    fill_kernel<<<edge_grid, 256, 0, sb>>>(edges, n_edges);
    if (fork) cudaEventRecord(evJ, s2);

    // Layer 0 projection (independent of the CSR build)
    proj_kernel<128, false><<<296, 256, smem0>>>(x, w_rel0, w_root0, b_rel0, Y, AA);

    // Join: gathers need the CSR
    if (fork) cudaStreamWaitEvent(0, evJ, 0);
    gather_kernel<<<gather_grid, 256>>>((const float4*)Y, (float4*)AA);

    // Layer 1 (ReLU fused on read)
    proj_kernel<64, true><<<592, 256, smem1>>>(AA, w_rel1, w_root1, b_rel1, Y, AB);
    gather_kernel<<<gather_grid, 256>>>((const float4*)Y, (float4*)AB);

    // Layer 2
    proj_kernel<64, true><<<592, 256, smem1>>>(AB, w_rel2, w_root2, b_rel2, Y, AA);
    gather_kernel<<<gather_grid, 256>>>((const float4*)Y, (float4*)AA);

    // Mean pool (ReLU fused) + head
    pool_kernel<<<pool_grid, 256>>>(AA, batch);
    head_kernel<<<1, 64>>>(hw1, hb1, hw2, hb2, out);
}